// round 1
// baseline (speedup 1.0000x reference)
#include <cuda_runtime.h>
#include <math.h>

#define T_HRZ   1024
#define NBATCH  128
#define NU_     64
#define NY_     64
#define NH_     256
#define NHC_    128          // complex channels
#define MROWS   (T_HRZ * NBATCH)   // 131072
#define CCH     16           // scan chunks
#define LCH     (T_HRZ / CCH)      // 64 steps per chunk

// ---------------- scratch (static __device__ — no allocations allowed) ------
__device__ float g_Bu[MROWS * NH_];     // 134 MB: Bu = (U @ (B*nf)^T), layout [t*NB+b][h]
__device__ float g_X [MROWS * NH_];     // 134 MB: scan states, same layout
__device__ float g_x0[NBATCH * NH_];
__device__ float g_lr[NHC_], g_li[NHC_], g_nf[NH_];
__device__ float g_lamLr[NHC_], g_lamLi[NHC_];
__device__ float g_sre[CCH * NBATCH * NHC_], g_sim[CCH * NBATCH * NHC_];
__device__ float g_cre[CCH * NBATCH * NHC_], g_cim[CCH * NBATCH * NHC_];

// ---------------- K0: lambda params, nf, lambda^L ----------------------------
__global__ void k_setup(const float* __restrict__ ar, const float* __restrict__ ai) {
    int h = threadIdx.x;
    if (h < NHC_) {
        float a  = fabsf(ar[h]);
        float r  = expf(-a);
        float th = 1.5707963267948966f * ai[h];
        float lr = r * cosf(th);
        float li = r * sinf(th);
        g_lr[h] = lr;
        g_li[h] = li;
        float nf = sqrtf(1.0f - expf(-2.0f * a));
        g_nf[h]        = nf;
        g_nf[h + NHC_] = nf;
        // lambda^LCH by repeated complex multiply
        float pr = 1.0f, pi = 0.0f;
        for (int i = 0; i < LCH; i++) {
            float nr = pr * lr - pi * li;
            pi       = pr * li + pi * lr;
            pr       = nr;
        }
        g_lamLr[h] = pr;
        g_lamLi[h] = pi;
    }
}

// ---------------- K_x0: x0 = y0 @ W_y2x^T + b_y2x ----------------------------
__global__ void k_x0(const float* __restrict__ y0, const float* __restrict__ W,
                     const float* __restrict__ bias) {
    __shared__ float yrow[NY_];
    int b = blockIdx.x;     // batch
    int h = threadIdx.x;    // 0..255
    if (h < NY_) yrow[h] = y0[b * NY_ + h];
    __syncthreads();
    float acc = bias[h];
    const float* w = W + h * NY_;
    #pragma unroll
    for (int k = 0; k < NY_; k++) acc = fmaf(yrow[k], w[k], acc);
    g_x0[b * NH_ + h] = acc;
}

// ---------------- K_Bu: Bu[m][n] = sum_k U[m][k] * B[n][k] * nf[n] -----------
// Tile: 64(M) x 64(N), K=64 fully resident. 256 threads, 4x4 register tile.
__global__ void k_bu(const float* __restrict__ U, const float* __restrict__ B) {
    __shared__ float As[64 * 68];  // [m][k], stride 68
    __shared__ float Bs[64 * 68];  // [k][n], stride 68 (transposed + nf-scaled)
    int tid = threadIdx.x;
    int m0  = blockIdx.x * 64;
    int n0  = blockIdx.y * 64;

    // load U tile, natural [m][k], float4
    #pragma unroll
    for (int l = 0; l < 4; l++) {
        int fid  = tid + l * 256;       // 0..1023
        int row  = fid >> 4;            // 0..63
        int colf = fid & 15;            // 0..15
        float4 v = *reinterpret_cast<const float4*>(U + (m0 + row) * NU_ + colf * 4);
        *reinterpret_cast<float4*>(&As[row * 68 + colf * 4]) = v;
    }
    // load B tile transposed with nf scale: Bs[k][n] = B[n0+n][k] * nf[n0+n]
    #pragma unroll
    for (int l = 0; l < 4; l++) {
        int fid  = tid + l * 256;
        int n    = fid >> 4;
        int colf = fid & 15;
        float s  = g_nf[n0 + n];
        float4 v = *reinterpret_cast<const float4*>(B + (n0 + n) * NU_ + colf * 4);
        Bs[(colf * 4 + 0) * 68 + n] = v.x * s;
        Bs[(colf * 4 + 1) * 68 + n] = v.y * s;
        Bs[(colf * 4 + 2) * 68 + n] = v.z * s;
        Bs[(colf * 4 + 3) * 68 + n] = v.w * s;
    }
    __syncthreads();

    int tx = tid & 15, ty = tid >> 4;
    int m4 = ty * 4, n4 = tx * 4;
    float acc[4][4] = {};
    #pragma unroll 16
    for (int k = 0; k < 64; k++) {
        float4 b4 = *reinterpret_cast<const float4*>(&Bs[k * 68 + n4]);
        float a0 = As[(m4 + 0) * 68 + k];
        float a1 = As[(m4 + 1) * 68 + k];
        float a2 = As[(m4 + 2) * 68 + k];
        float a3 = As[(m4 + 3) * 68 + k];
        acc[0][0] = fmaf(a0, b4.x, acc[0][0]); acc[0][1] = fmaf(a0, b4.y, acc[0][1]);
        acc[0][2] = fmaf(a0, b4.z, acc[0][2]); acc[0][3] = fmaf(a0, b4.w, acc[0][3]);
        acc[1][0] = fmaf(a1, b4.x, acc[1][0]); acc[1][1] = fmaf(a1, b4.y, acc[1][1]);
        acc[1][2] = fmaf(a1, b4.z, acc[1][2]); acc[1][3] = fmaf(a1, b4.w, acc[1][3]);
        acc[2][0] = fmaf(a2, b4.x, acc[2][0]); acc[2][1] = fmaf(a2, b4.y, acc[2][1]);
        acc[2][2] = fmaf(a2, b4.z, acc[2][2]); acc[2][3] = fmaf(a2, b4.w, acc[2][3]);
        acc[3][0] = fmaf(a3, b4.x, acc[3][0]); acc[3][1] = fmaf(a3, b4.y, acc[3][1]);
        acc[3][2] = fmaf(a3, b4.z, acc[3][2]); acc[3][3] = fmaf(a3, b4.w, acc[3][3]);
    }
    #pragma unroll
    for (int i = 0; i < 4; i++) {
        float4 out = make_float4(acc[i][0], acc[i][1], acc[i][2], acc[i][3]);
        *reinterpret_cast<float4*>(&g_Bu[(m0 + m4 + i) * NH_ + n0 + n4]) = out;
    }
}

// ---------------- scan phase A: per-chunk local suffix sums ------------------
__global__ void k_scan_local() {
    int hc = threadIdx.x;     // 0..127
    int b  = blockIdx.x;      // 0..127
    int c  = blockIdx.y;      // 0..15
    float lr = g_lr[hc], li = g_li[hc];
    float zr = 0.0f, zi = 0.0f;
    int base = ((c * LCH) * NBATCH + b) * NH_ + hc;
    #pragma unroll 4
    for (int i = 0; i < LCH; i++) {
        float ur = g_Bu[base];
        float ui = g_Bu[base + NHC_];
        float nr = fmaf(lr, zr, fmaf(-li, zi, ur));
        float ni = fmaf(li, zr, fmaf( lr, zi, ui));
        zr = nr; zi = ni;
        base += NBATCH * NH_;
    }
    int idx = (c * NBATCH + b) * NHC_ + hc;
    g_sre[idx] = zr;
    g_sim[idx] = zi;
}

// ---------------- scan phase B: carry scan over chunks -----------------------
__global__ void k_carry() {
    int hc = threadIdx.x;   // 0..127
    int b  = blockIdx.x;    // 0..127
    float pr = g_lamLr[hc], pi = g_lamLi[hc];
    float cr = g_x0[b * NH_ + hc];
    float ci = g_x0[b * NH_ + NHC_ + hc];
    for (int c = 0; c < CCH; c++) {
        int idx = (c * NBATCH + b) * NHC_ + hc;
        g_cre[idx] = cr;
        g_cim[idx] = ci;
        float nr = fmaf(pr, cr, fmaf(-pi, ci, g_sre[idx]));
        float ni = fmaf(pi, cr, fmaf( pr, ci, g_sim[idx]));
        cr = nr; ci = ni;
    }
}

// ---------------- scan phase C: expand chunks, write X -----------------------
__global__ void k_scan_expand() {
    int hc = threadIdx.x;
    int b  = blockIdx.x;
    int c  = blockIdx.y;
    float lr = g_lr[hc], li = g_li[hc];
    int idx = (c * NBATCH + b) * NHC_ + hc;
    float zr = g_cre[idx], zi = g_cim[idx];
    int base = ((c * LCH) * NBATCH + b) * NH_ + hc;
    #pragma unroll 4
    for (int i = 0; i < LCH; i++) {
        float ur = g_Bu[base];
        float ui = g_Bu[base + NHC_];
        float nr = fmaf(lr, zr, fmaf(-li, zi, ur));
        float ni = fmaf(li, zr, fmaf( lr, zi, ui));
        zr = nr; zi = ni;
        g_X[base]        = zr;
        g_X[base + NHC_] = zi;
        base += NBATCH * NH_;
    }
}

// ---------------- K_out: Y = X @ W_x2y^T + b_x2y -----------------------------
// Tile: 64(M) x 64(N=all), K=256 in 4 stages of 64. 256 threads, 4x4 per thread.
__global__ void k_out(const float* __restrict__ W, const float* __restrict__ bias,
                      float* __restrict__ Y) {
    __shared__ float As[64 * 68];  // [m][kk]
    __shared__ float Ws[64 * 68];  // [kk][n]
    int tid = threadIdx.x;
    int m0  = blockIdx.x * 64;
    int tx = tid & 15, ty = tid >> 4;
    int m4 = ty * 4, n4 = tx * 4;

    float acc[4][4];
    #pragma unroll
    for (int i = 0; i < 4; i++)
        #pragma unroll
        for (int j = 0; j < 4; j++) acc[i][j] = bias[n4 + j];

    for (int kt = 0; kt < 4; kt++) {
        int k0 = kt * 64;
        // load X tile natural [m][kk]
        #pragma unroll
        for (int l = 0; l < 4; l++) {
            int fid  = tid + l * 256;
            int row  = fid >> 4;
            int colf = fid & 15;
            float4 v = *reinterpret_cast<const float4*>(
                &g_X[(m0 + row) * NH_ + k0 + colf * 4]);
            *reinterpret_cast<float4*>(&As[row * 68 + colf * 4]) = v;
        }
        // load W tile transposed: Ws[kk][n] = W[n][k0+kk]
        #pragma unroll
        for (int l = 0; l < 4; l++) {
            int fid  = tid + l * 256;
            int n    = fid >> 4;
            int colf = fid & 15;
            float4 v = *reinterpret_cast<const float4*>(W + n * NH_ + k0 + colf * 4);
            Ws[(colf * 4 + 0) * 68 + n] = v.x;
            Ws[(colf * 4 + 1) * 68 + n] = v.y;
            Ws[(colf * 4 + 2) * 68 + n] = v.z;
            Ws[(colf * 4 + 3) * 68 + n] = v.w;
        }
        __syncthreads();
        #pragma unroll 16
        for (int k = 0; k < 64; k++) {
            float4 b4 = *reinterpret_cast<const float4*>(&Ws[k * 68 + n4]);
            float a0 = As[(m4 + 0) * 68 + k];
            float a1 = As[(m4 + 1) * 68 + k];
            float a2 = As[(m4 + 2) * 68 + k];
            float a3 = As[(m4 + 3) * 68 + k];
            acc[0][0] = fmaf(a0, b4.x, acc[0][0]); acc[0][1] = fmaf(a0, b4.y, acc[0][1]);
            acc[0][2] = fmaf(a0, b4.z, acc[0][2]); acc[0][3] = fmaf(a0, b4.w, acc[0][3]);
            acc[1][0] = fmaf(a1, b4.x, acc[1][0]); acc[1][1] = fmaf(a1, b4.y, acc[1][1]);
            acc[1][2] = fmaf(a1, b4.z, acc[1][2]); acc[1][3] = fmaf(a1, b4.w, acc[1][3]);
            acc[2][0] = fmaf(a2, b4.x, acc[2][0]); acc[2][1] = fmaf(a2, b4.y, acc[2][1]);
            acc[2][2] = fmaf(a2, b4.z, acc[2][2]); acc[2][3] = fmaf(a2, b4.w, acc[2][3]);
            acc[3][0] = fmaf(a3, b4.x, acc[3][0]); acc[3][1] = fmaf(a3, b4.y, acc[3][1]);
            acc[3][2] = fmaf(a3, b4.z, acc[3][2]); acc[3][3] = fmaf(a3, b4.w, acc[3][3]);
        }
        __syncthreads();
    }
    #pragma unroll
    for (int i = 0; i < 4; i++) {
        float4 out = make_float4(acc[i][0], acc[i][1], acc[i][2], acc[i][3]);
        *reinterpret_cast<float4*>(&Y[(m0 + m4 + i) * NY_ + n4]) = out;
    }
}

// ---------------- launch -----------------------------------------------------
extern "C" void kernel_launch(void* const* d_in, const int* in_sizes, int n_in,
                              void* d_out, int out_size) {
    const float* y0     = (const float*)d_in[0];
    const float* U      = (const float*)d_in[1];
    const float* lre    = (const float*)d_in[2];
    const float* lim    = (const float*)d_in[3];
    const float* B      = (const float*)d_in[4];
    const float* W_y2x  = (const float*)d_in[5];
    const float* b_y2x  = (const float*)d_in[6];
    const float* W_x2y  = (const float*)d_in[7];
    const float* b_x2y  = (const float*)d_in[8];
    float*       Y      = (float*)d_out;

    k_setup<<<1, 128>>>(lre, lim);
    k_x0<<<NBATCH, NH_>>>(y0, W_y2x, b_y2x);
    dim3 gBu(MROWS / 64, NH_ / 64);
    k_bu<<<gBu, 256>>>(U, B);
    dim3 gScan(NBATCH, CCH);
    k_scan_local<<<gScan, NHC_>>>();
    k_carry<<<NBATCH, NHC_>>>();
    k_scan_expand<<<gScan, NHC_>>>();
    k_out<<<MROWS / 64, 256>>>(W_x2y, b_x2y, Y);
}

// round 2
// speedup vs baseline: 1.9264x; 1.9264x over previous
#include <cuda_runtime.h>
#include <math.h>
#include <stdint.h>

#define T_HRZ   1024
#define NBATCH  128
#define NU_     64
#define NY_     64
#define NH_     256
#define NHC_    128
#define MROWS   (T_HRZ * NBATCH)
#define CCH     16
#define LCH     64

// strides (floats) for padded smem tiles — chosen for conflict-free MMA frag LDS
#define SU_STR  68     // [64 t ][64 u]
#define SB_STR  68     // [256 h][64 u]
#define SX_STR  268    // [64 t ][256 h]
#define SW_STR  260    // [64 n ][256 k]

// ---------------- scratch ----------------------------------------------------
__device__ float g_Bu[MROWS * NH_];                      // tile-contiguous [(b*16+c)][t][h]
__device__ float g_x0[NBATCH * NH_];
__device__ float g_lr[NHC_], g_li[NHC_], g_nf[NH_];
__device__ float g_lamLr[NHC_], g_lamLi[NHC_];
__device__ float g_sre[CCH * NBATCH * NHC_], g_sim[CCH * NBATCH * NHC_];
__device__ float g_cre[CCH * NBATCH * NHC_], g_cim[CCH * NBATCH * NHC_];

// ---------------- mma helpers ------------------------------------------------
__device__ __forceinline__ void split_tf32(float a, uint32_t& hi, uint32_t& lo) {
    uint32_t h;
    asm("cvt.rna.tf32.f32 %0, %1;" : "=r"(h) : "f"(a));
    float r = a - __uint_as_float(h);
    asm("cvt.rna.tf32.f32 %0, %1;" : "=r"(lo) : "f"(r));
    hi = h;
}

__device__ __forceinline__ void mma_tf32(float* c, const uint32_t* a, const uint32_t* b) {
    asm volatile(
        "mma.sync.aligned.m16n8k8.row.col.f32.tf32.tf32.f32 "
        "{%0,%1,%2,%3}, {%4,%5,%6,%7}, {%8,%9}, {%0,%1,%2,%3};"
        : "+f"(c[0]), "+f"(c[1]), "+f"(c[2]), "+f"(c[3])
        : "r"(a[0]), "r"(a[1]), "r"(a[2]), "r"(a[3]), "r"(b[0]), "r"(b[1]));
}

// ---------------- K0: lambda params, nf, lambda^L ----------------------------
__global__ void k_setup(const float* __restrict__ ar, const float* __restrict__ ai) {
    int h = threadIdx.x;
    if (h < NHC_) {
        float a  = fabsf(ar[h]);
        float r  = expf(-a);
        float th = 1.5707963267948966f * ai[h];
        float lr = r * cosf(th);
        float li = r * sinf(th);
        g_lr[h] = lr;
        g_li[h] = li;
        float nf = sqrtf(1.0f - expf(-2.0f * a));
        g_nf[h]        = nf;
        g_nf[h + NHC_] = nf;
        float pr = 1.0f, pi = 0.0f;
        for (int i = 0; i < LCH; i++) {
            float nr = pr * lr - pi * li;
            pi       = pr * li + pi * lr;
            pr       = nr;
        }
        g_lamLr[h] = pr;
        g_lamLi[h] = pi;
    }
}

// ---------------- x0 = y0 @ W_y2x^T + b_y2x ----------------------------------
__global__ void k_x0(const float* __restrict__ y0, const float* __restrict__ W,
                     const float* __restrict__ bias) {
    __shared__ float yrow[NY_];
    int b = blockIdx.x;
    int h = threadIdx.x;
    if (h < NY_) yrow[h] = y0[b * NY_ + h];
    __syncthreads();
    float acc = bias[h];
    const float* w = W + h * NY_;
    #pragma unroll
    for (int k = 0; k < NY_; k++) acc = fmaf(yrow[k], w[k], acc);
    g_x0[b * NH_ + h] = acc;
}

// ---------------- K1: fused Bu GEMM (3xTF32) + local suffix scan -------------
// block = (b, c). Computes Bu tile [64 t][256 h], scans locally, stores tile.
__global__ void __launch_bounds__(256, 1)
k_bu_scan(const float* __restrict__ U, const float* __restrict__ B) {
    extern __shared__ float sm[];
    float* sU  = sm;                       // 64 x SU_STR
    float* sB  = sU + 64 * SU_STR;         // 256 x SB_STR
    float* sBu = sB + 256 * SB_STR;        // 64 x SX_STR

    int tid = threadIdx.x;
    int b   = blockIdx.x;
    int c   = blockIdx.y;

    // load U tile [t][u]: row t_global = c*64+row
    #pragma unroll
    for (int p = 0; p < 4; p++) {
        int idx = tid + p * 256;           // 0..1023
        int row = idx >> 4;
        int cf  = idx & 15;
        float4 v = *reinterpret_cast<const float4*>(
            U + ((size_t)(c * 64 + row) * NBATCH + b) * NU_ + cf * 4);
        *reinterpret_cast<float4*>(&sU[row * SU_STR + cf * 4]) = v;
    }
    // load B scaled by nf: sB[h][u]
    #pragma unroll
    for (int p = 0; p < 16; p++) {
        int idx = tid + p * 256;           // 0..4095
        int row = idx >> 4;                // 0..255
        int cf  = idx & 15;
        float s = g_nf[row];
        float4 v = *reinterpret_cast<const float4*>(B + row * NU_ + cf * 4);
        v.x *= s; v.y *= s; v.z *= s; v.w *= s;
        *reinterpret_cast<float4*>(&sB[row * SB_STR + cf * 4]) = v;
    }
    __syncthreads();

    // GEMM: M=64 x N=256 x K=64. 8 warps; warp w owns n-slice [w*32, w*32+32)
    int warp = tid >> 5;
    int lane = tid & 31;
    int g  = lane >> 2;
    int tg = lane & 3;
    int wn0 = warp * 32;

    float C[4][4][4];
    #pragma unroll
    for (int mt = 0; mt < 4; mt++)
        #pragma unroll
        for (int nt = 0; nt < 4; nt++)
            #pragma unroll
            for (int i = 0; i < 4; i++) C[mt][nt][i] = 0.0f;

    #pragma unroll
    for (int k0 = 0; k0 < 64; k0 += 8) {
        uint32_t Ah[4][4], Al[4][4];
        #pragma unroll
        for (int mt = 0; mt < 4; mt++) {
            int m0 = mt * 16;
            split_tf32(sU[(m0 + g    ) * SU_STR + k0 + tg    ], Ah[mt][0], Al[mt][0]);
            split_tf32(sU[(m0 + g + 8) * SU_STR + k0 + tg    ], Ah[mt][1], Al[mt][1]);
            split_tf32(sU[(m0 + g    ) * SU_STR + k0 + tg + 4], Ah[mt][2], Al[mt][2]);
            split_tf32(sU[(m0 + g + 8) * SU_STR + k0 + tg + 4], Ah[mt][3], Al[mt][3]);
        }
        uint32_t Bh[4][2], Bl[4][2];
        #pragma unroll
        for (int nt = 0; nt < 4; nt++) {
            int n0 = wn0 + nt * 8;
            split_tf32(sB[(n0 + g) * SB_STR + k0 + tg    ], Bh[nt][0], Bl[nt][0]);
            split_tf32(sB[(n0 + g) * SB_STR + k0 + tg + 4], Bh[nt][1], Bl[nt][1]);
        }
        #pragma unroll
        for (int mt = 0; mt < 4; mt++)
            #pragma unroll
            for (int nt = 0; nt < 4; nt++) {
                mma_tf32(C[mt][nt], Ah[mt], Bh[nt]);
                mma_tf32(C[mt][nt], Ah[mt], Bl[nt]);
                mma_tf32(C[mt][nt], Al[mt], Bh[nt]);
            }
    }

    // fragments -> sBu
    #pragma unroll
    for (int mt = 0; mt < 4; mt++)
        #pragma unroll
        for (int nt = 0; nt < 4; nt++) {
            int m0 = mt * 16;
            int n0 = wn0 + nt * 8 + tg * 2;
            sBu[(m0 + g    ) * SX_STR + n0    ] = C[mt][nt][0];
            sBu[(m0 + g    ) * SX_STR + n0 + 1] = C[mt][nt][1];
            sBu[(m0 + g + 8) * SX_STR + n0    ] = C[mt][nt][2];
            sBu[(m0 + g + 8) * SX_STR + n0 + 1] = C[mt][nt][3];
        }
    __syncthreads();

    if (tid < 128) {
        // warps 0-3: local suffix scan (zero initial state)
        int hc = tid;
        float lr = g_lr[hc], li = g_li[hc];
        float zr = 0.0f, zi = 0.0f;
        #pragma unroll 8
        for (int t = 0; t < 64; t++) {
            float ur = sBu[t * SX_STR + hc];
            float ui = sBu[t * SX_STR + NHC_ + hc];
            float nr = fmaf(lr, zr, fmaf(-li, zi, ur));
            float ni = fmaf(li, zr, fmaf( lr, zi, ui));
            zr = nr; zi = ni;
        }
        int idx = (c * NBATCH + b) * NHC_ + hc;
        g_sre[idx] = zr;
        g_sim[idx] = zi;
    } else {
        // warps 4-7: store Bu tile to global (tile-contiguous)
        int t2 = tid - 128;
        size_t base = (size_t)(b * CCH + c) * 64 * NH_;
        #pragma unroll
        for (int p = 0; p < 32; p++) {
            int idx = t2 + p * 128;        // 0..4095 float4s
            int row = idx >> 6;
            int cf  = idx & 63;
            float4 v = *reinterpret_cast<const float4*>(&sBu[row * SX_STR + cf * 4]);
            *reinterpret_cast<float4*>(&g_Bu[base + row * NH_ + cf * 4]) = v;
        }
    }
}

// ---------------- carry scan over chunks -------------------------------------
__global__ void k_carry() {
    int hc = threadIdx.x;
    int b  = blockIdx.x;
    float pr = g_lamLr[hc], pi = g_lamLi[hc];
    float cr = g_x0[b * NH_ + hc];
    float ci = g_x0[b * NH_ + NHC_ + hc];
    for (int c = 0; c < CCH; c++) {
        int idx = (c * NBATCH + b) * NHC_ + hc;
        g_cre[idx] = cr;
        g_cim[idx] = ci;
        float nr = fmaf(pr, cr, fmaf(-pi, ci, g_sre[idx]));
        float ni = fmaf(pi, cr, fmaf( pr, ci, g_sim[idx]));
        cr = nr; ci = ni;
    }
}

// ---------------- K2: fused scan-expand + output GEMM (3xTF32) ---------------
// block = (b, c). Loads Bu tile, expands X in smem, Y = X @ W^T + bias.
__global__ void __launch_bounds__(256, 1)
k_expand_out(const float* __restrict__ W, const float* __restrict__ bias,
             float* __restrict__ Y) {
    extern __shared__ float sm[];
    float* sX = sm;                        // 64 x SX_STR (Bu -> X in place; later Y staging)
    float* sW = sX + 64 * SX_STR;          // 64 x SW_STR

    int tid = threadIdx.x;
    int b   = blockIdx.x;
    int c   = blockIdx.y;

    // load Bu tile
    size_t base = (size_t)(b * CCH + c) * 64 * NH_;
    #pragma unroll
    for (int p = 0; p < 16; p++) {
        int idx = tid + p * 256;           // 0..4095 float4s
        int row = idx >> 6;
        int cf  = idx & 63;
        float4 v = *reinterpret_cast<const float4*>(&g_Bu[base + row * NH_ + cf * 4]);
        *reinterpret_cast<float4*>(&sX[row * SX_STR + cf * 4]) = v;
    }
    // load W [64][256]
    #pragma unroll
    for (int p = 0; p < 16; p++) {
        int idx = tid + p * 256;           // 0..4095
        int row = idx >> 6;
        int cf  = idx & 63;
        float4 v = *reinterpret_cast<const float4*>(W + row * NH_ + cf * 4);
        *reinterpret_cast<float4*>(&sW[row * SW_STR + cf * 4]) = v;
    }
    __syncthreads();

    // scan expand in place
    if (tid < 128) {
        int hc = tid;
        float lr = g_lr[hc], li = g_li[hc];
        int idx = (c * NBATCH + b) * NHC_ + hc;
        float zr = g_cre[idx], zi = g_cim[idx];
        #pragma unroll 8
        for (int t = 0; t < 64; t++) {
            float ur = sX[t * SX_STR + hc];
            float ui = sX[t * SX_STR + NHC_ + hc];
            float nr = fmaf(lr, zr, fmaf(-li, zi, ur));
            float ni = fmaf(li, zr, fmaf( lr, zi, ui));
            zr = nr; zi = ni;
            sX[t * SX_STR + hc]        = zr;
            sX[t * SX_STR + NHC_ + hc] = zi;
        }
    }
    __syncthreads();

    // GEMM: M=64 x N=64 x K=256. 8 warps: (wm 0..1) x (wn 0..3)
    int warp = tid >> 5;
    int lane = tid & 31;
    int g  = lane >> 2;
    int tg = lane & 3;
    int wm0 = (warp >> 2) * 32;
    int wn0 = (warp & 3) * 16;

    float C[2][2][4];
    #pragma unroll
    for (int mt = 0; mt < 2; mt++)
        #pragma unroll
        for (int nt = 0; nt < 2; nt++) {
            float b0 = bias[wn0 + nt * 8 + tg * 2];
            float b1 = bias[wn0 + nt * 8 + tg * 2 + 1];
            C[mt][nt][0] = b0; C[mt][nt][1] = b1;
            C[mt][nt][2] = b0; C[mt][nt][3] = b1;
        }

    #pragma unroll 4
    for (int k0 = 0; k0 < 256; k0 += 8) {
        uint32_t Ah[2][4], Al[2][4];
        #pragma unroll
        for (int mt = 0; mt < 2; mt++) {
            int m0 = wm0 + mt * 16;
            split_tf32(sX[(m0 + g    ) * SX_STR + k0 + tg    ], Ah[mt][0], Al[mt][0]);
            split_tf32(sX[(m0 + g + 8) * SX_STR + k0 + tg    ], Ah[mt][1], Al[mt][1]);
            split_tf32(sX[(m0 + g    ) * SX_STR + k0 + tg + 4], Ah[mt][2], Al[mt][2]);
            split_tf32(sX[(m0 + g + 8) * SX_STR + k0 + tg + 4], Ah[mt][3], Al[mt][3]);
        }
        uint32_t Bh[2][2], Bl[2][2];
        #pragma unroll
        for (int nt = 0; nt < 2; nt++) {
            int n0 = wn0 + nt * 8;
            split_tf32(sW[(n0 + g) * SW_STR + k0 + tg    ], Bh[nt][0], Bl[nt][0]);
            split_tf32(sW[(n0 + g) * SW_STR + k0 + tg + 4], Bh[nt][1], Bl[nt][1]);
        }
        #pragma unroll
        for (int mt = 0; mt < 2; mt++)
            #pragma unroll
            for (int nt = 0; nt < 2; nt++) {
                mma_tf32(C[mt][nt], Ah[mt], Bh[nt]);
                mma_tf32(C[mt][nt], Ah[mt], Bl[nt]);
                mma_tf32(C[mt][nt], Al[mt], Bh[nt]);
            }
    }
    __syncthreads();   // sX reads done before reuse as Y staging

    // fragments -> smem Y staging (stride 68), then coalesced global store
    float* sY = sX;
    #pragma unroll
    for (int mt = 0; mt < 2; mt++)
        #pragma unroll
        for (int nt = 0; nt < 2; nt++) {
            int m0 = wm0 + mt * 16;
            int n0 = wn0 + nt * 8 + tg * 2;
            sY[(m0 + g    ) * 68 + n0    ] = C[mt][nt][0];
            sY[(m0 + g    ) * 68 + n0 + 1] = C[mt][nt][1];
            sY[(m0 + g + 8) * 68 + n0    ] = C[mt][nt][2];
            sY[(m0 + g + 8) * 68 + n0 + 1] = C[mt][nt][3];
        }
    __syncthreads();

    #pragma unroll
    for (int p = 0; p < 4; p++) {
        int idx = tid + p * 256;           // 0..1023 float4s
        int row = idx >> 4;
        int cf  = idx & 15;
        float4 v = *reinterpret_cast<const float4*>(&sY[row * 68 + cf * 4]);
        *reinterpret_cast<float4*>(
            Y + ((size_t)(c * 64 + row) * NBATCH + b) * NY_ + cf * 4) = v;
    }
}

// ---------------- launch -----------------------------------------------------
extern "C" void kernel_launch(void* const* d_in, const int* in_sizes, int n_in,
                              void* d_out, int out_size) {
    const float* y0     = (const float*)d_in[0];
    const float* U      = (const float*)d_in[1];
    const float* lre    = (const float*)d_in[2];
    const float* lim    = (const float*)d_in[3];
    const float* B      = (const float*)d_in[4];
    const float* W_y2x  = (const float*)d_in[5];
    const float* b_y2x  = (const float*)d_in[6];
    const float* W_x2y  = (const float*)d_in[7];
    const float* b_x2y  = (const float*)d_in[8];
    float*       Y      = (float*)d_out;

    const int smem1 = (64 * SU_STR + 256 * SB_STR + 64 * SX_STR) * 4;
    const int smem2 = (64 * SX_STR + 64 * SW_STR) * 4;
    cudaFuncSetAttribute(k_bu_scan,    cudaFuncAttributeMaxDynamicSharedMemorySize, smem1);
    cudaFuncSetAttribute(k_expand_out, cudaFuncAttributeMaxDynamicSharedMemorySize, smem2);

    k_setup<<<1, 128>>>(lre, lim);
    k_x0<<<NBATCH, NH_>>>(y0, W_y2x, b_y2x);
    dim3 grid(NBATCH, CCH);
    k_bu_scan<<<grid, 256, smem1>>>(U, B);
    k_carry<<<NBATCH, NHC_>>>();
    k_expand_out<<<grid, 256, smem2>>>(W_x2y, b_x2y, Y);
}

// round 4
// speedup vs baseline: 3.2252x; 1.6742x over previous
#include <cuda_runtime.h>
#include <cuda_bf16.h>
#include <math.h>
#include <stdint.h>

#define NBATCH  128
#define NH_     256
#define NHC_    128
#define NU_     64
#define NY_     64
#define CCH     16

// ---- smem layout (bytes) ----------------------------------------------------
// sBphi/sBplo : B' = B*nf split, [256 h][68 pad] bf16 planes
// sWhi/sWlo   : W_x2y split,     [64 n][260 pad] bf16 planes
// sU planes   : U tile split,    [64 t][68 pad]  bf16 (aliased with sY fp32 [64][68])
// sBuX        : Bu fp32 -> X fp32 -> X packed(hi,lo), [64 t][260 pad] 32-bit words
// sx0         : 256 floats
#define OFF_BPHI 0
#define OFF_BPLO 34816
#define OFF_WHI  69632
#define OFF_WLO  102912
#define OFF_U    136192
#define OFF_ULO  144896
#define OFF_BUX  153600
#define OFF_X0   220160
#define SMEM_TOTAL 221184

// ---- helpers ----------------------------------------------------------------
__device__ __forceinline__ void split2(float a0, float a1, uint32_t& hi, uint32_t& lo) {
    __nv_bfloat16 h0 = __float2bfloat16_rn(a0);
    __nv_bfloat16 h1 = __float2bfloat16_rn(a1);
    float r0 = a0 - __bfloat162float(h0);
    float r1 = a1 - __bfloat162float(h1);
    __nv_bfloat16 l0 = __float2bfloat16_rn(r0);
    __nv_bfloat16 l1 = __float2bfloat16_rn(r1);
    hi = ((uint32_t)__bfloat16_as_ushort(h1) << 16) | __bfloat16_as_ushort(h0);
    lo = ((uint32_t)__bfloat16_as_ushort(l1) << 16) | __bfloat16_as_ushort(l0);
}

__device__ __forceinline__ void mma_bf16(float* c, const uint32_t* a, const uint32_t* b) {
    asm volatile(
        "mma.sync.aligned.m16n8k16.row.col.f32.bf16.bf16.f32 "
        "{%0,%1,%2,%3}, {%4,%5,%6,%7}, {%8,%9}, {%0,%1,%2,%3};"
        : "+f"(c[0]), "+f"(c[1]), "+f"(c[2]), "+f"(c[3])
        : "r"(a[0]), "r"(a[1]), "r"(a[2]), "r"(a[3]), "r"(b[0]), "r"(b[1]));
}

// ---- the fused kernel -------------------------------------------------------
__global__ void __launch_bounds__(256, 1)
k_fused(const float* __restrict__ y0,   const float* __restrict__ U,
        const float* __restrict__ lre,  const float* __restrict__ lim,
        const float* __restrict__ B,    const float* __restrict__ W_y2x,
        const float* __restrict__ b_y2x,const float* __restrict__ W_x2y,
        const float* __restrict__ b_x2y,float* __restrict__ Y) {
    extern __shared__ char sm[];
    int tid  = threadIdx.x;
    int b    = blockIdx.x;
    int warp = tid >> 5, lane = tid & 31;
    int g = lane >> 2, tg = lane & 3;

    // ---- preload B' = B * nf, split to bf16 planes (thread = one h row) ----
    {
        int h  = tid;
        int hc = h & (NHC_ - 1);
        float a  = fabsf(__ldg(lre + hc));
        float nf = sqrtf(1.0f - expf(-2.0f * a));
        const float4* src = reinterpret_cast<const float4*>(B + h * NU_);
        #pragma unroll
        for (int q = 0; q < 16; q++) {
            float4 v = __ldg(src + q);
            v.x *= nf; v.y *= nf; v.z *= nf; v.w *= nf;
            uint32_t h01, l01, h23, l23;
            split2(v.x, v.y, h01, l01);
            split2(v.z, v.w, h23, l23);
            int k = q * 4;
            *(uint32_t*)(sm + OFF_BPHI + (h * 68 + k    ) * 2) = h01;
            *(uint32_t*)(sm + OFF_BPHI + (h * 68 + k + 2) * 2) = h23;
            *(uint32_t*)(sm + OFF_BPLO + (h * 68 + k    ) * 2) = l01;
            *(uint32_t*)(sm + OFF_BPLO + (h * 68 + k + 2) * 2) = l23;
        }
    }
    // ---- preload W_x2y split ----
    {
        int n = tid >> 2, part = tid & 3;
        const float4* src = reinterpret_cast<const float4*>(W_x2y + n * NH_ + part * 64);
        #pragma unroll
        for (int q = 0; q < 16; q++) {
            float4 v = __ldg(src + q);
            uint32_t h01, l01, h23, l23;
            split2(v.x, v.y, h01, l01);
            split2(v.z, v.w, h23, l23);
            int k = part * 64 + q * 4;
            *(uint32_t*)(sm + OFF_WHI + (n * 260 + k    ) * 2) = h01;
            *(uint32_t*)(sm + OFF_WHI + (n * 260 + k + 2) * 2) = h23;
            *(uint32_t*)(sm + OFF_WLO + (n * 260 + k    ) * 2) = l01;
            *(uint32_t*)(sm + OFF_WLO + (n * 260 + k + 2) * 2) = l23;
        }
    }
    // ---- x0[h] = b_y2x[h] + sum_k y0[b][k] * W_y2x[h][k] ----
    {
        float acc = __ldg(b_y2x + tid);
        const float* w = W_y2x + tid * NY_;
        const float* y = y0 + b * NY_;
        #pragma unroll
        for (int k = 0; k < NY_; k++) acc = fmaf(__ldg(y + k), __ldg(w + k), acc);
        ((float*)(sm + OFF_X0))[tid] = acc;
    }
    // ---- prefetch U(chunk 0) into registers ----
    int urow = tid >> 2, uq = tid & 3;
    float4 ureg[4];
    {
        const float4* src = reinterpret_cast<const float4*>(
            U + ((size_t)urow * NBATCH + b) * NU_);
        #pragma unroll
        for (int j = 0; j < 4; j++) ureg[j] = __ldg(src + uq * 4 + j);
    }
    __syncthreads();

    // ---- scan params + carry (threads 0..127) ----
    float czr = 0.f, czi = 0.f, slr = 0.f, sli = 0.f;
    if (tid < NHC_) {
        float a  = fabsf(__ldg(lre + tid));
        float r  = expf(-a);
        float th = 1.5707963267948966f * __ldg(lim + tid);
        slr = r * cosf(th);
        sli = r * sinf(th);
        czr = ((float*)(sm + OFF_X0))[tid];
        czi = ((float*)(sm + OFF_X0))[tid + NHC_];
    }

    for (int c = 0; c < CCH; c++) {
        // -- STS U(c) split --
        #pragma unroll
        for (int j = 0; j < 4; j++) {
            float4 v = ureg[j];
            uint32_t h01, l01, h23, l23;
            split2(v.x, v.y, h01, l01);
            split2(v.z, v.w, h23, l23);
            int k = uq * 16 + j * 4;
            *(uint32_t*)(sm + OFF_U   + (urow * 68 + k    ) * 2) = h01;
            *(uint32_t*)(sm + OFF_U   + (urow * 68 + k + 2) * 2) = h23;
            *(uint32_t*)(sm + OFF_ULO + (urow * 68 + k    ) * 2) = l01;
            *(uint32_t*)(sm + OFF_ULO + (urow * 68 + k + 2) * 2) = l23;
        }
        __syncthreads();
        // -- prefetch U(c+1) --
        if (c < CCH - 1) {
            const float4* src = reinterpret_cast<const float4*>(
                U + ((size_t)((c + 1) * 64 + urow) * NBATCH + b) * NU_);
            #pragma unroll
            for (int j = 0; j < 4; j++) ureg[j] = __ldg(src + uq * 4 + j);
        }

        // -- Bu GEMM: M=64 N=256 K=64 (warp n-slice of 32) --
        {
            int wn0 = warp * 32;
            float C[4][4][4];
            #pragma unroll
            for (int mt = 0; mt < 4; mt++)
                #pragma unroll
                for (int nt = 0; nt < 4; nt++)
                    #pragma unroll
                    for (int i = 0; i < 4; i++) C[mt][nt][i] = 0.0f;

            #pragma unroll
            for (int k0 = 0; k0 < 64; k0 += 16) {
                uint32_t Ah[4][4], Al[4][4];
                #pragma unroll
                for (int mt = 0; mt < 4; mt++) {
                    int r = mt * 16 + g;
                    int k = k0 + 2 * tg;
                    Ah[mt][0] = *(const uint32_t*)(sm + OFF_U   + (r * 68 + k) * 2);
                    Al[mt][0] = *(const uint32_t*)(sm + OFF_ULO + (r * 68 + k) * 2);
                    Ah[mt][1] = *(const uint32_t*)(sm + OFF_U   + ((r + 8) * 68 + k) * 2);
                    Al[mt][1] = *(const uint32_t*)(sm + OFF_ULO + ((r + 8) * 68 + k) * 2);
                    Ah[mt][2] = *(const uint32_t*)(sm + OFF_U   + (r * 68 + k + 8) * 2);
                    Al[mt][2] = *(const uint32_t*)(sm + OFF_ULO + (r * 68 + k + 8) * 2);
                    Ah[mt][3] = *(const uint32_t*)(sm + OFF_U   + ((r + 8) * 68 + k + 8) * 2);
                    Al[mt][3] = *(const uint32_t*)(sm + OFF_ULO + ((r + 8) * 68 + k + 8) * 2);
                }
                uint32_t Bh[4][2], Bl[4][2];
                #pragma unroll
                for (int nt = 0; nt < 4; nt++) {
                    int n = wn0 + nt * 8 + g;
                    int k = k0 + 2 * tg;
                    Bh[nt][0] = *(const uint32_t*)(sm + OFF_BPHI + (n * 68 + k) * 2);
                    Bl[nt][0] = *(const uint32_t*)(sm + OFF_BPLO + (n * 68 + k) * 2);
                    Bh[nt][1] = *(const uint32_t*)(sm + OFF_BPHI + (n * 68 + k + 8) * 2);
                    Bl[nt][1] = *(const uint32_t*)(sm + OFF_BPLO + (n * 68 + k + 8) * 2);
                }
                #pragma unroll
                for (int mt = 0; mt < 4; mt++)
                    #pragma unroll
                    for (int nt = 0; nt < 4; nt++) {
                        mma_bf16(C[mt][nt], Ah[mt], Bh[nt]);
                        mma_bf16(C[mt][nt], Ah[mt], Bl[nt]);
                        mma_bf16(C[mt][nt], Al[mt], Bh[nt]);
                    }
            }
            // epilogue: fp32 into sBuX
            float* bux = (float*)(sm + OFF_BUX);
            #pragma unroll
            for (int mt = 0; mt < 4; mt++)
                #pragma unroll
                for (int nt = 0; nt < 4; nt++) {
                    int r = mt * 16 + g;
                    int n = wn0 + nt * 8 + 2 * tg;
                    *(float2*)&bux[r * 260 + n]       = make_float2(C[mt][nt][0], C[mt][nt][1]);
                    *(float2*)&bux[(r + 8) * 260 + n] = make_float2(C[mt][nt][2], C[mt][nt][3]);
                }
        }
        __syncthreads();

        // -- scan (threads 0..127), in place fp32 --
        if (tid < NHC_) {
            float* bux = (float*)(sm + OFF_BUX);
            float zr = czr, zi = czi;
            #pragma unroll 4
            for (int t = 0; t < 64; t++) {
                float ur = bux[t * 260 + tid];
                float ui = bux[t * 260 + NHC_ + tid];
                float nr = fmaf(slr, zr, fmaf(-sli, zi, ur));
                float ni = fmaf(sli, zr, fmaf( slr, zi, ui));
                zr = nr; zi = ni;
                bux[t * 260 + tid]        = zr;
                bux[t * 260 + NHC_ + tid] = zi;
            }
            czr = zr; czi = zi;
        }
        __syncthreads();

        // -- split pass: fp32 X -> packed (hi<<16|lo), in place --
        {
            uint32_t* bux = (uint32_t*)(sm + OFF_BUX);
            #pragma unroll 8
            for (int p = 0; p < 64; p++) {
                int idx = tid + p * 256;
                int off = (idx >> 8) * 260 + (idx & 255);
                float v = __uint_as_float(bux[off]);
                __nv_bfloat16 h = __float2bfloat16_rn(v);
                __nv_bfloat16 l = __float2bfloat16_rn(v - __bfloat162float(h));
                bux[off] = ((uint32_t)__bfloat16_as_ushort(h) << 16) |
                           __bfloat16_as_ushort(l);
            }
        }
        __syncthreads();

        // -- out GEMM: M=64 N=64 K=256 (warp grid 2x4, tile 32x16) --
        {
            int wm0 = (warp >> 2) * 32, wn0 = (warp & 3) * 16;
            const uint32_t* bux = (const uint32_t*)(sm + OFF_BUX);
            float C[2][2][4];
            #pragma unroll
            for (int mt = 0; mt < 2; mt++)
                #pragma unroll
                for (int nt = 0; nt < 2; nt++) {
                    int n = wn0 + nt * 8 + 2 * tg;
                    float b0 = __ldg(b_x2y + n);
                    float b1 = __ldg(b_x2y + n + 1);
                    C[mt][nt][0] = b0; C[mt][nt][1] = b1;
                    C[mt][nt][2] = b0; C[mt][nt][3] = b1;
                }
            #pragma unroll 4
            for (int k0 = 0; k0 < 256; k0 += 16) {
                uint32_t Ah[2][4], Al[2][4];
                #pragma unroll
                for (int mt = 0; mt < 2; mt++) {
                    int r = wm0 + mt * 16 + g;
                    int k = k0 + 2 * tg;
                    #pragma unroll
                    for (int pos = 0; pos < 4; pos++) {
                        int rr = r + ((pos & 1) ? 8 : 0);
                        int kk = k + ((pos & 2) ? 8 : 0);
                        uint32_t w0 = bux[rr * 260 + kk];
                        uint32_t w1 = bux[rr * 260 + kk + 1];
                        Ah[mt][pos] = __byte_perm(w0, w1, 0x7632);
                        Al[mt][pos] = __byte_perm(w0, w1, 0x5410);
                    }
                }
                uint32_t Bh[2][2], Bl[2][2];
                #pragma unroll
                for (int nt = 0; nt < 2; nt++) {
                    int n = wn0 + nt * 8 + g;
                    int k = k0 + 2 * tg;
                    Bh[nt][0] = *(const uint32_t*)(sm + OFF_WHI + (n * 260 + k) * 2);
                    Bl[nt][0] = *(const uint32_t*)(sm + OFF_WLO + (n * 260 + k) * 2);
                    Bh[nt][1] = *(const uint32_t*)(sm + OFF_WHI + (n * 260 + k + 8) * 2);
                    Bl[nt][1] = *(const uint32_t*)(sm + OFF_WLO + (n * 260 + k + 8) * 2);
                }
                #pragma unroll
                for (int mt = 0; mt < 2; mt++)
                    #pragma unroll
                    for (int nt = 0; nt < 2; nt++) {
                        mma_bf16(C[mt][nt], Ah[mt], Bh[nt]);
                        mma_bf16(C[mt][nt], Ah[mt], Bl[nt]);
                        mma_bf16(C[mt][nt], Al[mt], Bh[nt]);
                    }
            }
            // frags -> sY (aliases sU; U(c) consumed, U(c+1) in regs)
            float* sY = (float*)(sm + OFF_U);
            #pragma unroll
            for (int mt = 0; mt < 2; mt++)
                #pragma unroll
                for (int nt = 0; nt < 2; nt++) {
                    int r = wm0 + mt * 16 + g;
                    int n = wn0 + nt * 8 + 2 * tg;
                    *(float2*)&sY[r * 68 + n]       = make_float2(C[mt][nt][0], C[mt][nt][1]);
                    *(float2*)&sY[(r + 8) * 68 + n] = make_float2(C[mt][nt][2], C[mt][nt][3]);
                }
        }
        __syncthreads();
        // -- cooperative Y store --
        {
            const float* sY = (const float*)(sm + OFF_U);
            #pragma unroll
            for (int p = 0; p < 4; p++) {
                int idx = tid + p * 256;
                int row = idx >> 4, cf = idx & 15;
                float4 v = *(const float4*)&sY[row * 68 + cf * 4];
                *reinterpret_cast<float4*>(
                    Y + ((size_t)(c * 64 + row) * NBATCH + b) * NY_ + cf * 4) = v;
            }
        }
        __syncthreads();   // sY/sU free for next chunk's U STS
    }
}

// ---- launch -----------------------------------------------------------------
extern "C" void kernel_launch(void* const* d_in, const int* in_sizes, int n_in,
                              void* d_out, int out_size) {
    const float* y0     = (const float*)d_in[0];
    const float* U      = (const float*)d_in[1];
    const float* lre    = (const float*)d_in[2];
    const float* lim    = (const float*)d_in[3];
    const float* B      = (const float*)d_in[4];
    const float* W_y2x  = (const float*)d_in[5];
    const float* b_y2x  = (const float*)d_in[6];
    const float* W_x2y  = (const float*)d_in[7];
    const float* b_x2y  = (const float*)d_in[8];
    float*       Y      = (float*)d_out;

    cudaFuncSetAttribute(k_fused, cudaFuncAttributeMaxDynamicSharedMemorySize,
                         SMEM_TOTAL);
    k_fused<<<NBATCH, 256, SMEM_TOTAL>>>(y0, U, lre, lim, B, W_y2x, b_y2x,
                                         W_x2y, b_x2y, Y);
}

// round 6
// speedup vs baseline: 4.0093x; 1.2431x over previous
#include <cuda_runtime.h>
#include <cuda_bf16.h>
#include <math.h>
#include <stdint.h>

#define NBATCH  128
#define NH_     256
#define NHC_    128
#define NU_     64
#define NY_     64
#define NCHUNK  32
#define TCH     32          // timesteps per chunk

// ---- smem layout (bytes) ----------------------------------------------------
#define OFF_BPHI 0          // B' hi  [256][72] bf16
#define OFF_BPLO 36864      // B' lo
#define OFF_WHI  73728      // W hi   [64][264] bf16
#define OFF_WLO  107520     // W lo
#define OFF_UHI  141312     // U hi   [32][72] bf16
#define OFF_ULO  145920     // U lo
#define OFF_BUX0 150528     // BuX buf0 [32][268] fp32/packed
#define OFF_BUX1 184832     // BuX buf1
#define OFF_X0   219136     // 256 fp32
#define SMEM_TOTAL 220160

#define SB_STR   72
#define SW_STR   264
#define SX_STR   268

// ---- helpers ----------------------------------------------------------------
__device__ __forceinline__ uint32_t sptr(const void* p) {
    return (uint32_t)__cvta_generic_to_shared(p);
}
__device__ __forceinline__ void split2(float a0, float a1, uint32_t& hi, uint32_t& lo) {
    __nv_bfloat16 h0 = __float2bfloat16_rn(a0);
    __nv_bfloat16 h1 = __float2bfloat16_rn(a1);
    __nv_bfloat16 l0 = __float2bfloat16_rn(a0 - __bfloat162float(h0));
    __nv_bfloat16 l1 = __float2bfloat16_rn(a1 - __bfloat162float(h1));
    hi = ((uint32_t)__bfloat16_as_ushort(h1) << 16) | __bfloat16_as_ushort(h0);
    lo = ((uint32_t)__bfloat16_as_ushort(l1) << 16) | __bfloat16_as_ushort(l0);
}
__device__ __forceinline__ uint32_t pack_hl(float v) {
    __nv_bfloat16 h = __float2bfloat16_rn(v);
    __nv_bfloat16 l = __float2bfloat16_rn(v - __bfloat162float(h));
    return ((uint32_t)__bfloat16_as_ushort(h) << 16) | __bfloat16_as_ushort(l);
}
__device__ __forceinline__ void mma_bf16(float* c, const uint32_t* a, const uint32_t* b) {
    asm volatile(
        "mma.sync.aligned.m16n8k16.row.col.f32.bf16.bf16.f32 "
        "{%0,%1,%2,%3}, {%4,%5,%6,%7}, {%8,%9}, {%0,%1,%2,%3};"
        : "+f"(c[0]), "+f"(c[1]), "+f"(c[2]), "+f"(c[3])
        : "r"(a[0]), "r"(a[1]), "r"(a[2]), "r"(a[3]), "r"(b[0]), "r"(b[1]));
}
#define LDSM_X4(r0, r1, r2, r3, addr)                                        \
    asm volatile("ldmatrix.sync.aligned.m8n8.x4.shared.b16 {%0,%1,%2,%3}, [%4];" \
                 : "=r"(r0), "=r"(r1), "=r"(r2), "=r"(r3) : "r"(addr))
#define BAR_SYNC2(id)   asm volatile("bar.sync %0, 256;"   :: "r"(id) : "memory")
#define BAR_ARRIVE2(id) asm volatile("bar.arrive %0, 256;" :: "r"(id) : "memory")
#define BAR_P()         asm volatile("bar.sync 1, 128;" ::: "memory")
// barrier ids: 1 = producer internal; full = 2+buf; empty = 4+buf

// ---- the fused warp-specialized kernel --------------------------------------
__global__ void __launch_bounds__(256, 1)
k_fused(const float* __restrict__ y0,   const float* __restrict__ U,
        const float* __restrict__ lre,  const float* __restrict__ lim,
        const float* __restrict__ B,    const float* __restrict__ W_y2x,
        const float* __restrict__ b_y2x,const float* __restrict__ W_x2y,
        const float* __restrict__ b_x2y,float* __restrict__ Y) {
    extern __shared__ char sm[];
    int tid  = threadIdx.x;
    int b    = blockIdx.x;
    int lane = tid & 31;
    int g = lane >> 2, tg = lane & 3;
    int j8 = lane >> 3, r8 = lane & 7;   // ldmatrix addressing

    // ======== init: B' planes (all 256 threads, one h-row each) ========
    {
        int h  = tid;
        int hc = h & (NHC_ - 1);
        float a  = fabsf(__ldg(lre + hc));
        float nf = sqrtf(1.0f - expf(-2.0f * a));
        const float4* src = reinterpret_cast<const float4*>(B + h * NU_);
        #pragma unroll
        for (int q = 0; q < 16; q++) {
            float4 v = __ldg(src + q);
            v.x *= nf; v.y *= nf; v.z *= nf; v.w *= nf;
            uint32_t h01, l01, h23, l23;
            split2(v.x, v.y, h01, l01);
            split2(v.z, v.w, h23, l23);
            int k = q * 4;
            *(uint32_t*)(sm + OFF_BPHI + (h * SB_STR + k    ) * 2) = h01;
            *(uint32_t*)(sm + OFF_BPHI + (h * SB_STR + k + 2) * 2) = h23;
            *(uint32_t*)(sm + OFF_BPLO + (h * SB_STR + k    ) * 2) = l01;
            *(uint32_t*)(sm + OFF_BPLO + (h * SB_STR + k + 2) * 2) = l23;
        }
    }
    // ======== init: W planes ========
    {
        int n = tid >> 2, part = tid & 3;
        const float4* src = reinterpret_cast<const float4*>(W_x2y + n * NH_ + part * 64);
        #pragma unroll
        for (int q = 0; q < 16; q++) {
            float4 v = __ldg(src + q);
            uint32_t h01, l01, h23, l23;
            split2(v.x, v.y, h01, l01);
            split2(v.z, v.w, h23, l23);
            int k = part * 64 + q * 4;
            *(uint32_t*)(sm + OFF_WHI + (n * SW_STR + k    ) * 2) = h01;
            *(uint32_t*)(sm + OFF_WHI + (n * SW_STR + k + 2) * 2) = h23;
            *(uint32_t*)(sm + OFF_WLO + (n * SW_STR + k    ) * 2) = l01;
            *(uint32_t*)(sm + OFF_WLO + (n * SW_STR + k + 2) * 2) = l23;
        }
    }
    // ======== init: x0 ========
    {
        float acc = __ldg(b_y2x + tid);
        const float* w = W_y2x + tid * NY_;
        const float* y = y0 + b * NY_;
        #pragma unroll
        for (int k = 0; k < NY_; k++) acc = fmaf(__ldg(y + k), __ldg(w + k), acc);
        ((float*)(sm + OFF_X0))[tid] = acc;
    }

    // ======== producer-side U(0) prefetch ========
    int urow = tid >> 2, uq = tid & 3;   // producer threads (tid<128): row 0..31
    float4 ureg[4];
    if (tid < 128) {
        const float4* src = reinterpret_cast<const float4*>(
            U + ((size_t)urow * NBATCH + b) * NU_);
        #pragma unroll
        for (int j = 0; j < 4; j++) ureg[j] = __ldg(src + uq * 4 + j);
    }
    __syncthreads();

    if (tid < 128) {
        // =================== PRODUCER (warps 0-3) ===================
        float a  = fabsf(__ldg(lre + tid));
        float rr_ = expf(-a);
        float th = 1.5707963267948966f * __ldg(lim + tid);
        float slr = rr_ * cosf(th);
        float sli = rr_ * sinf(th);
        float czr = ((float*)(sm + OFF_X0))[tid];
        float czi = ((float*)(sm + OFF_X0))[tid + NHC_];
        int warp = tid >> 5;
        int wn0  = warp * 64;

        for (int c = 0; c < NCHUNK; c++) {
            int buf = c & 1;
            char* bux_c = sm + (buf ? OFF_BUX1 : OFF_BUX0);
            BAR_SYNC2(4 + buf);              // wait buffer empty

            // STS U(c) split planes
            #pragma unroll
            for (int j = 0; j < 4; j++) {
                float4 v = ureg[j];
                uint32_t h01, l01, h23, l23;
                split2(v.x, v.y, h01, l01);
                split2(v.z, v.w, h23, l23);
                int k = uq * 16 + j * 4;
                *(uint32_t*)(sm + OFF_UHI + (urow * SB_STR + k    ) * 2) = h01;
                *(uint32_t*)(sm + OFF_UHI + (urow * SB_STR + k + 2) * 2) = h23;
                *(uint32_t*)(sm + OFF_ULO + (urow * SB_STR + k    ) * 2) = l01;
                *(uint32_t*)(sm + OFF_ULO + (urow * SB_STR + k + 2) * 2) = l23;
            }
            BAR_P();
            // prefetch U(c+1)
            if (c < NCHUNK - 1) {
                const float4* src = reinterpret_cast<const float4*>(
                    U + ((size_t)((c + 1) * TCH + urow) * NBATCH + b) * NU_);
                #pragma unroll
                for (int j = 0; j < 4; j++) ureg[j] = __ldg(src + uq * 4 + j);
            }

            // ---- Bu GEMM: M=32 N=256(warp slice 64) K=64 ----
            float C[2][8][4];
            #pragma unroll
            for (int mt = 0; mt < 2; mt++)
                #pragma unroll
                for (int nt = 0; nt < 8; nt++)
                    #pragma unroll
                    for (int i = 0; i < 4; i++) C[mt][nt][i] = 0.0f;

            #pragma unroll
            for (int k0 = 0; k0 < 64; k0 += 16) {
                int arow = (j8 & 1) * 8 + r8;
                int acol = k0 + (j8 >> 1) * 8;
                uint32_t Ah[2][4], Al[2][4];
                #pragma unroll
                for (int mt = 0; mt < 2; mt++) {
                    uint32_t ah = sptr(sm + OFF_UHI + ((mt * 16 + arow) * SB_STR + acol) * 2);
                    uint32_t al = sptr(sm + OFF_ULO + ((mt * 16 + arow) * SB_STR + acol) * 2);
                    LDSM_X4(Ah[mt][0], Ah[mt][1], Ah[mt][2], Ah[mt][3], ah);
                    LDSM_X4(Al[mt][0], Al[mt][1], Al[mt][2], Al[mt][3], al);
                }
                uint32_t Bh[8][2], Bl[8][2];
                #pragma unroll
                for (int ntp = 0; ntp < 4; ntp++) {
                    int nrow = wn0 + (ntp * 2 + (j8 >> 1)) * 8 + r8;
                    int bcol = k0 + (j8 & 1) * 8;
                    uint32_t bh = sptr(sm + OFF_BPHI + (nrow * SB_STR + bcol) * 2);
                    uint32_t bl = sptr(sm + OFF_BPLO + (nrow * SB_STR + bcol) * 2);
                    LDSM_X4(Bh[ntp*2][0], Bh[ntp*2][1], Bh[ntp*2+1][0], Bh[ntp*2+1][1], bh);
                    LDSM_X4(Bl[ntp*2][0], Bl[ntp*2][1], Bl[ntp*2+1][0], Bl[ntp*2+1][1], bl);
                }
                #pragma unroll
                for (int mt = 0; mt < 2; mt++)
                    #pragma unroll
                    for (int nt = 0; nt < 8; nt++) {
                        mma_bf16(C[mt][nt], Ah[mt], Bh[nt]);
                        mma_bf16(C[mt][nt], Ah[mt], Bl[nt]);
                        mma_bf16(C[mt][nt], Al[mt], Bh[nt]);
                    }
            }
            // epilogue -> BuX fp32
            float* bx = (float*)bux_c;
            #pragma unroll
            for (int mt = 0; mt < 2; mt++)
                #pragma unroll
                for (int nt = 0; nt < 8; nt++) {
                    int r = mt * 16 + g;
                    int n = wn0 + nt * 8 + 2 * tg;
                    *(float2*)&bx[r * SX_STR + n]       = make_float2(C[mt][nt][0], C[mt][nt][1]);
                    *(float2*)&bx[(r + 8) * SX_STR + n] = make_float2(C[mt][nt][2], C[mt][nt][3]);
                }
            BAR_P();

            // ---- scan (all 128 P threads), write packed in place ----
            {
                uint32_t* bxu = (uint32_t*)bux_c;
                float zr = czr, zi = czi;
                #pragma unroll 4
                for (int t = 0; t < TCH; t++) {
                    float ur = bx[t * SX_STR + tid];
                    float ui = bx[t * SX_STR + NHC_ + tid];
                    float nr = fmaf(slr, zr, fmaf(-sli, zi, ur));
                    float ni = fmaf(sli, zr, fmaf( slr, zi, ui));
                    zr = nr; zi = ni;
                    bxu[t * SX_STR + tid]        = pack_hl(zr);
                    bxu[t * SX_STR + NHC_ + tid] = pack_hl(zi);
                }
                czr = zr; czi = zi;
            }
            BAR_ARRIVE2(2 + buf);            // buffer full
        }
    } else {
        // =================== CONSUMER (warps 4-7) ===================
        int qw  = (tid >> 5) - 4;            // 0..3
        int wn0 = qw * 16;
        BAR_ARRIVE2(4);                      // prime both empties
        BAR_ARRIVE2(5);
        float bias0[2], bias1[2];
        #pragma unroll
        for (int nt = 0; nt < 2; nt++) {
            bias0[nt] = __ldg(b_x2y + wn0 + nt * 8 + 2 * tg);
            bias1[nt] = __ldg(b_x2y + wn0 + nt * 8 + 2 * tg + 1);
        }

        for (int c = 0; c < NCHUNK; c++) {
            int buf = c & 1;
            const uint32_t* bxu = (const uint32_t*)(sm + (buf ? OFF_BUX1 : OFF_BUX0));
            BAR_SYNC2(2 + buf);              // wait full

            float C[2][2][4];
            #pragma unroll
            for (int mt = 0; mt < 2; mt++)
                #pragma unroll
                for (int nt = 0; nt < 2; nt++) {
                    C[mt][nt][0] = bias0[nt]; C[mt][nt][1] = bias1[nt];
                    C[mt][nt][2] = bias0[nt]; C[mt][nt][3] = bias1[nt];
                }
            #pragma unroll 4
            for (int k0 = 0; k0 < 256; k0 += 16) {
                uint32_t Ah[2][4], Al[2][4];
                #pragma unroll
                for (int mt = 0; mt < 2; mt++) {
                    #pragma unroll
                    for (int pos = 0; pos < 4; pos++) {
                        int rr = mt * 16 + g + ((pos & 1) ? 8 : 0);
                        int kk = k0 + 2 * tg + ((pos & 2) ? 8 : 0);
                        uint32_t w0 = bxu[rr * SX_STR + kk];
                        uint32_t w1 = bxu[rr * SX_STR + kk + 1];
                        Ah[mt][pos] = __byte_perm(w0, w1, 0x7632);
                        Al[mt][pos] = __byte_perm(w0, w1, 0x5410);
                    }
                }
                uint32_t Bh[2][2], Bl[2][2];
                {
                    int nrow = wn0 + (j8 >> 1) * 8 + r8;
                    int bcol = k0 + (j8 & 1) * 8;
                    uint32_t bh = sptr(sm + OFF_WHI + (nrow * SW_STR + bcol) * 2);
                    uint32_t bl = sptr(sm + OFF_WLO + (nrow * SW_STR + bcol) * 2);
                    LDSM_X4(Bh[0][0], Bh[0][1], Bh[1][0], Bh[1][1], bh);
                    LDSM_X4(Bl[0][0], Bl[0][1], Bl[1][0], Bl[1][1], bl);
                }
                #pragma unroll
                for (int mt = 0; mt < 2; mt++)
                    #pragma unroll
                    for (int nt = 0; nt < 2; nt++) {
                        mma_bf16(C[mt][nt], Ah[mt], Bh[nt]);
                        mma_bf16(C[mt][nt], Ah[mt], Bl[nt]);
                        mma_bf16(C[mt][nt], Al[mt], Bh[nt]);
                    }
            }
            BAR_ARRIVE2(4 + buf);            // buffer empty (before Y store: regs only)

            // Y store directly from fragments
            #pragma unroll
            for (int mt = 0; mt < 2; mt++)
                #pragma unroll
                for (int nt = 0; nt < 2; nt++) {
                    int n  = wn0 + nt * 8 + 2 * tg;
                    int t0 = c * TCH + mt * 16 + g;
                    *reinterpret_cast<float2*>(
                        Y + ((size_t)t0 * NBATCH + b) * NY_ + n) =
                        make_float2(C[mt][nt][0], C[mt][nt][1]);
                    *reinterpret_cast<float2*>(
                        Y + ((size_t)(t0 + 8) * NBATCH + b) * NY_ + n) =
                        make_float2(C[mt][nt][2], C[mt][nt][3]);
                }
        }
    }
}

// ---- launch -----------------------------------------------------------------
extern "C" void kernel_launch(void* const* d_in, const int* in_sizes, int n_in,
                              void* d_out, int out_size) {
    const float* y0     = (const float*)d_in[0];
    const float* U      = (const float*)d_in[1];
    const float* lre    = (const float*)d_in[2];
    const float* lim    = (const float*)d_in[3];
    const float* B      = (const float*)d_in[4];
    const float* W_y2x  = (const float*)d_in[5];
    const float* b_y2x  = (const float*)d_in[6];
    const float* W_x2y  = (const float*)d_in[7];
    const float* b_x2y  = (const float*)d_in[8];
    float*       Y      = (float*)d_out;

    cudaFuncSetAttribute(k_fused, cudaFuncAttributeMaxDynamicSharedMemorySize,
                         SMEM_TOTAL);
    k_fused<<<NBATCH, 256, SMEM_TOTAL>>>(y0, U, lre, lim, B, W_y2x, b_y2x,
                                         W_x2y, b_x2y, Y);
}